// round 13
// baseline (speedup 1.0000x reference)
#include <cuda_runtime.h>
#include <cuda_fp16.h>
#include <cstdint>

#define NNODES 100000
#define EMAX   1600000
#define NGRAPH 64

// ---------------- device scratch ----------------
__device__ int    g_cnt[NNODES];
__device__ int    g_rowstart[NNODES];
__device__ int    g_cursor[NNODES];
__device__ unsigned long long g_state[128];   // decoupled-lookback state
__device__ int    g_csrsrc[EMAX];
__device__ float  g_dis[NNODES];
__device__ __half g_hs1h[NNODES * 32];    // fp16: dis * (x @ W1)   (row = 64B)
__device__ __half2 g_hs2h[NNODES * 32];   // fp16x2: dis * (lrelu(layer1) @ W2)  (row = 128B)
__device__ int    g_pool[NGRAPH * 64];

#define FLAG_A (1ull << 62)
#define FLAG_P (2ull << 62)

// ---------------- helpers ----------------
__device__ __forceinline__ int fenc(float v) {
    int i = __float_as_int(v);
    return i >= 0 ? i : (i ^ 0x7FFFFFFF);
}
__device__ __forceinline__ float fdec(int i) {
    return __int_as_float(i >= 0 ? i : (i ^ 0x7FFFFFFF));
}
__device__ __forceinline__ float lrelu(float v) { return v > 0.0f ? v : 0.1f * v; }

#define ENC_NEG_INF ((int)0x807FFFFF)
#define FNEG_INF    __int_as_float(0xFF800000)

// ---------------- kernels ----------------

// histogram of dst (int4-vectorized); block 0 also zeroes scan state + inits pool
__global__ void k_count(const int* __restrict__ dst, int E) {
    if (blockIdx.x == 0) {
        if (threadIdx.x < 128) g_state[threadIdx.x] = 0ull;
        for (int i = threadIdx.x; i < NGRAPH * 64; i += 256) g_pool[i] = ENC_NEG_INF;
    }
    int t = blockIdx.x * blockDim.x + threadIdx.x;
    int e4 = E >> 2;
    if (t < e4) {
        int4 d = reinterpret_cast<const int4*>(dst)[t];
        atomicAdd(&g_cnt[d.x], 1);
        atomicAdd(&g_cnt[d.y], 1);
        atomicAdd(&g_cnt[d.z], 1);
        atomicAdd(&g_cnt[d.w], 1);
    } else {
        int e = e4 * 4 + (t - e4);
        if (e < E) atomicAdd(&g_cnt[dst[e]], 1);
    }
}

// single-pass decoupled-lookback exclusive scan of g_cnt -> g_rowstart/g_cursor; also g_dis
__global__ void k_scanlb(int Nn) {
    __shared__ int sT[256];
    __shared__ int sPrefix;
    int t = threadIdx.x;
    int b = blockIdx.x;
    int base = b * 1024 + t * 4;
    int v0 = (base + 0 < Nn) ? g_cnt[base + 0] : 0;
    int v1 = (base + 1 < Nn) ? g_cnt[base + 1] : 0;
    int v2 = (base + 2 < Nn) ? g_cnt[base + 2] : 0;
    int v3 = (base + 3 < Nn) ? g_cnt[base + 3] : 0;
    if (base + 0 < Nn) g_dis[base + 0] = rsqrtf((float)v0 + 1.0f);
    if (base + 1 < Nn) g_dis[base + 1] = rsqrtf((float)v1 + 1.0f);
    if (base + 2 < Nn) g_dis[base + 2] = rsqrtf((float)v2 + 1.0f);
    if (base + 3 < Nn) g_dis[base + 3] = rsqrtf((float)v3 + 1.0f);
    int tot = v0 + v1 + v2 + v3;
    sT[t] = tot;
    __syncthreads();
    for (int off = 1; off < 256; off <<= 1) {
        int x = 0;
        if (t >= off) x = sT[t - off];
        __syncthreads();
        if (t >= off) sT[t] += x;
        __syncthreads();
    }
    int myExc = sT[t] - tot;
    int blockTotal = sT[255];

    if (t == 0) {
        if (b == 0) {
            atomicExch(&g_state[0], FLAG_P | (unsigned int)blockTotal);
            sPrefix = 0;
        } else {
            atomicExch(&g_state[b], FLAG_A | (unsigned int)blockTotal);
            int run = 0;
            int idx = b - 1;
            while (true) {
                unsigned long long s = atomicAdd(&g_state[idx], 0ull);
                unsigned long long fl = s >> 62;
                if (fl == 2ull) { run += (int)(s & 0xFFFFFFFFull); break; }
                if (fl == 1ull) { run += (int)(s & 0xFFFFFFFFull); idx--; }
            }
            atomicExch(&g_state[b], FLAG_P | (unsigned int)(run + blockTotal));
            sPrefix = run;
        }
    }
    __syncthreads();

    int rs = sPrefix + myExc;
    if (base + 0 < Nn) { g_rowstart[base + 0] = rs; g_cursor[base + 0] = rs; } rs += v0;
    if (base + 1 < Nn) { g_rowstart[base + 1] = rs; g_cursor[base + 1] = rs; } rs += v1;
    if (base + 2 < Nn) { g_rowstart[base + 2] = rs; g_cursor[base + 2] = rs; } rs += v2;
    if (base + 3 < Nn) { g_rowstart[base + 3] = rs; g_cursor[base + 3] = rs; }
}

// fused: CSR fill (scatter) + gemm1 (hs1 = fp16(dis * x@W1))
__global__ void k_fillgemm(const int* __restrict__ src, const int* __restrict__ dst,
                           const float* __restrict__ x, const float* __restrict__ W1,
                           int E, int Nn) {
    __shared__ float sW[128 * 32];
    for (int i = threadIdx.x; i < 128 * 32; i += blockDim.x) sW[i] = W1[i];
    __syncthreads();

    int gtid = blockIdx.x * blockDim.x + threadIdx.x;
    int nthr = gridDim.x * blockDim.x;

    int e4 = E >> 2;
    for (int t = gtid; t < e4; t += nthr) {
        int4 d = reinterpret_cast<const int4*>(dst)[t];
        int4 sc = reinterpret_cast<const int4*>(src)[t];
        g_csrsrc[atomicAdd(&g_cursor[d.x], 1)] = sc.x;
        g_csrsrc[atomicAdd(&g_cursor[d.y], 1)] = sc.y;
        g_csrsrc[atomicAdd(&g_cursor[d.z], 1)] = sc.z;
        g_csrsrc[atomicAdd(&g_cursor[d.w], 1)] = sc.w;
    }
    for (int e = e4 * 4 + gtid; e < E; e += nthr)
        g_csrsrc[atomicAdd(&g_cursor[dst[e]], 1)] = src[e];

    int gw = gtid >> 5;
    int nw = nthr >> 5;
    int lane = threadIdx.x & 31;
    for (int node = gw; node < Nn; node += nw) {
        const float* xr = x + (size_t)node * 128;
        float acc = 0.0f;
#pragma unroll
        for (int kt = 0; kt < 4; kt++) {
            float xk = xr[kt * 32 + lane];
#pragma unroll
            for (int kk = 0; kk < 32; kk++) {
                float xv = __shfl_sync(0xFFFFFFFFu, xk, kk);
                acc = fmaf(xv, sW[(kt * 32 + kk) * 32 + lane], acc);
            }
        }
        g_hs1h[(size_t)node * 32 + lane] = __float2half_rn(g_dis[node] * acc);
    }
}

// layer-1 aggregation (dual-neighbor half2 gather) + lrelu + GEMM2
__global__ void k_agg1(const float* __restrict__ b1, const float* __restrict__ W2, int Nn) {
    __shared__ float sW[32 * 64];
    for (int i = threadIdx.x; i < 32 * 64; i += blockDim.x) sW[i] = W2[i];
    __syncthreads();
    int warp = (blockIdx.x * blockDim.x + threadIdx.x) >> 5;
    int lane = threadIdx.x & 31;
    if (warp >= Nn) return;

    int grpN = lane >> 4;     // which of the 2 neighbors this lane serves
    int sub  = lane & 15;     // feature pair (2*sub, 2*sub+1)
    const __half2* h2 = reinterpret_cast<const __half2*>(g_hs1h);

    int rs = g_rowstart[warp];
    int cnt = g_cnt[warp];
    float2 accA = {0.f, 0.f}, accB = {0.f, 0.f};
    for (int base = 0; base < cnt; base += 32) {
        int rem = cnt - base;
        int m = rem < 32 ? rem : 32;
        int sidx = 0;
        if (lane < m) sidx = g_csrsrc[rs + base + lane];
        int k = 0;
        for (; k + 4 <= m; k += 4) {
            int sA = __shfl_sync(0xFFFFFFFFu, sidx, k + grpN);
            int sB = __shfl_sync(0xFFFFFFFFu, sidx, k + 2 + grpN);
            float2 fA = __half22float2(__ldg(&h2[(size_t)sA * 16 + sub]));
            float2 fB = __half22float2(__ldg(&h2[(size_t)sB * 16 + sub]));
            accA.x += fA.x; accA.y += fA.y;
            accB.x += fB.x; accB.y += fB.y;
        }
        for (; k + 2 <= m; k += 2) {
            int sA = __shfl_sync(0xFFFFFFFFu, sidx, k + grpN);
            float2 fA = __half22float2(__ldg(&h2[(size_t)sA * 16 + sub]));
            accA.x += fA.x; accA.y += fA.y;
        }
        if (k < m) {
            int s = __shfl_sync(0xFFFFFFFFu, sidx, k);
            if (grpN == 0) {
                float2 f = __half22float2(__ldg(&h2[(size_t)s * 16 + sub]));
                accA.x += f.x; accA.y += f.y;
            }
        }
    }
    float2 acc;
    acc.x = accA.x + accB.x;
    acc.y = accA.y + accB.y;
    acc.x += __shfl_xor_sync(0xFFFFFFFFu, acc.x, 16);
    acc.y += __shfl_xor_sync(0xFFFFFFFFu, acc.y, 16);

    float d = g_dis[warp];
    float2 selff = __half22float2(h2[(size_t)warp * 16 + sub]);
    float2 b1p = reinterpret_cast<const float2*>(b1)[sub];
    float vx = lrelu(d * (acc.x + selff.x) + b1p.x);
    float vy = lrelu(d * (acc.y + selff.y) + b1p.y);

    // GEMM2: feature kk lives at lane kk>>1 (x=even, y=odd); lane produces (2*lane, 2*lane+1)
    const float2* sWp = reinterpret_cast<const float2*>(sW);
    float o0 = 0.f, o1 = 0.f;
#pragma unroll
    for (int kk = 0; kk < 32; kk++) {
        float xv = __shfl_sync(0xFFFFFFFFu, (kk & 1) ? vy : vx, kk >> 1);
        float2 w = sWp[kk * 32 + lane];
        o0 = fmaf(xv, w.x, o0);
        o1 = fmaf(xv, w.y, o1);
    }
    g_hs2h[(size_t)warp * 32 + lane] = __floats2half2_rn(d * o0, d * o1);
}

// layer-2 aggregation (dual-neighbor uint2 gather) + bias + fused global max pool
__global__ void k_agg2(const float* __restrict__ b2, const int* __restrict__ batch, int Nn) {
    __shared__ float sv[8][64];
    __shared__ int sb[8];
    int wid = threadIdx.x >> 5;
    int lane = threadIdx.x & 31;
    int node = blockIdx.x * 8 + wid;
    bool valid = node < Nn;

    if (lane == 0) sb[wid] = valid ? batch[node] : -1;

    int grpN = lane >> 4;     // which of the 2 neighbors
    int sub  = lane & 15;     // feature quad (4*sub .. 4*sub+3)
    const uint2* r2 = reinterpret_cast<const uint2*>(g_hs2h);   // row = 16 uint2

    if (valid) {
        int rs = g_rowstart[node];
        int cnt = g_cnt[node];
        float2 aA0 = {0.f, 0.f}, aA1 = {0.f, 0.f};
        float2 aB0 = {0.f, 0.f}, aB1 = {0.f, 0.f};
        for (int base = 0; base < cnt; base += 32) {
            int rem = cnt - base;
            int m = rem < 32 ? rem : 32;
            int sidx = 0;
            if (lane < m) sidx = g_csrsrc[rs + base + lane];
            int k = 0;
            for (; k + 4 <= m; k += 4) {
                int sA = __shfl_sync(0xFFFFFFFFu, sidx, k + grpN);
                int sB = __shfl_sync(0xFFFFFFFFu, sidx, k + 2 + grpN);
                uint2 uA = __ldg(&r2[(size_t)sA * 16 + sub]);
                uint2 uB = __ldg(&r2[(size_t)sB * 16 + sub]);
                float2 fA0 = __half22float2(__halves2half2(
                    __ushort_as_half((unsigned short)(uA.x & 0xFFFF)),
                    __ushort_as_half((unsigned short)(uA.x >> 16))));
                float2 fA1 = __half22float2(__halves2half2(
                    __ushort_as_half((unsigned short)(uA.y & 0xFFFF)),
                    __ushort_as_half((unsigned short)(uA.y >> 16))));
                float2 fB0 = __half22float2(__halves2half2(
                    __ushort_as_half((unsigned short)(uB.x & 0xFFFF)),
                    __ushort_as_half((unsigned short)(uB.x >> 16))));
                float2 fB1 = __half22float2(__halves2half2(
                    __ushort_as_half((unsigned short)(uB.y & 0xFFFF)),
                    __ushort_as_half((unsigned short)(uB.y >> 16))));
                aA0.x += fA0.x; aA0.y += fA0.y;
                aA1.x += fA1.x; aA1.y += fA1.y;
                aB0.x += fB0.x; aB0.y += fB0.y;
                aB1.x += fB1.x; aB1.y += fB1.y;
            }
            for (; k + 2 <= m; k += 2) {
                int sA = __shfl_sync(0xFFFFFFFFu, sidx, k + grpN);
                uint2 uA = __ldg(&r2[(size_t)sA * 16 + sub]);
                float2 fA0 = __half22float2(__halves2half2(
                    __ushort_as_half((unsigned short)(uA.x & 0xFFFF)),
                    __ushort_as_half((unsigned short)(uA.x >> 16))));
                float2 fA1 = __half22float2(__halves2half2(
                    __ushort_as_half((unsigned short)(uA.y & 0xFFFF)),
                    __ushort_as_half((unsigned short)(uA.y >> 16))));
                aA0.x += fA0.x; aA0.y += fA0.y;
                aA1.x += fA1.x; aA1.y += fA1.y;
            }
            if (k < m) {
                int s = __shfl_sync(0xFFFFFFFFu, sidx, k);
                if (grpN == 0) {
                    uint2 u = __ldg(&r2[(size_t)s * 16 + sub]);
                    float2 f0 = __half22float2(__halves2half2(
                        __ushort_as_half((unsigned short)(u.x & 0xFFFF)),
                        __ushort_as_half((unsigned short)(u.x >> 16))));
                    float2 f1 = __half22float2(__halves2half2(
                        __ushort_as_half((unsigned short)(u.y & 0xFFFF)),
                        __ushort_as_half((unsigned short)(u.y >> 16))));
                    aA0.x += f0.x; aA0.y += f0.y;
                    aA1.x += f1.x; aA1.y += f1.y;
                }
            }
        }
        float a0 = aA0.x + aB0.x, a1 = aA0.y + aB0.y;
        float a2 = aA1.x + aB1.x, a3 = aA1.y + aB1.y;
        a0 += __shfl_xor_sync(0xFFFFFFFFu, a0, 16);
        a1 += __shfl_xor_sync(0xFFFFFFFFu, a1, 16);
        a2 += __shfl_xor_sync(0xFFFFFFFFu, a2, 16);
        a3 += __shfl_xor_sync(0xFFFFFFFFu, a3, 16);

        if (grpN == 0) {
            uint2 su = __ldg(&r2[(size_t)node * 16 + sub]);
            float2 s0 = __half22float2(__halves2half2(
                __ushort_as_half((unsigned short)(su.x & 0xFFFF)),
                __ushort_as_half((unsigned short)(su.x >> 16))));
            float2 s1 = __half22float2(__halves2half2(
                __ushort_as_half((unsigned short)(su.y & 0xFFFF)),
                __ushort_as_half((unsigned short)(su.y >> 16))));
            float4 bb = reinterpret_cast<const float4*>(b2)[sub];
            float d = g_dis[node];
            float* o = &sv[wid][sub * 4];
            o[0] = d * (a0 + s0.x) + bb.x;
            o[1] = d * (a1 + s0.y) + bb.y;
            o[2] = d * (a2 + s1.x) + bb.z;
            o[3] = d * (a3 + s1.y) + bb.w;
        }
    }
    __syncthreads();

    if (threadIdx.x < 64) {
        int f = threadIdx.x;
        int curg = -1;
        float mx = FNEG_INF;
        for (int w = 0; w < 8; w++) {
            int bg = sb[w];
            if (bg < 0) continue;
            float val = sv[w][f];
            if (bg != curg) {
                if (curg >= 0) atomicMax(&g_pool[curg * 64 + f], fenc(mx));
                curg = bg;
                mx = FNEG_INF;
            }
            mx = fmaxf(mx, val);
        }
        if (curg >= 0) atomicMax(&g_pool[curg * 64 + f], fenc(mx));
    }
}

// MLP head, one block per graph: 64 -> 128 -> 64 -> 1
__global__ void k_mlp(const float* __restrict__ Wl1, const float* __restrict__ bl1,
                      const float* __restrict__ Wl2, const float* __restrict__ bl2,
                      const float* __restrict__ Wl3, const float* __restrict__ bl3,
                      float* __restrict__ out) {
    __shared__ float sg[64];
    __shared__ float st1[128];
    __shared__ float st2[64];
    int g = blockIdx.x;
    int t = threadIdx.x;

    if (t < 64) sg[t] = fdec(g_pool[g * 64 + t]);
    __syncthreads();
    {
        float s = bl1[t];
#pragma unroll 8
        for (int k = 0; k < 64; k++) s = fmaf(sg[k], Wl1[k * 128 + t], s);
        st1[t] = lrelu(s);
    }
    __syncthreads();
    if (t < 64) {
        float s = bl2[t];
#pragma unroll 8
        for (int k = 0; k < 128; k++) s = fmaf(st1[k], Wl2[k * 64 + t], s);
        st2[t] = lrelu(s);
    }
    __syncthreads();
    __shared__ float red[2];
    if (t < 64) {
        float p = st2[t] * Wl3[t];
#pragma unroll
        for (int off = 16; off > 0; off >>= 1)
            p += __shfl_down_sync(0xFFFFFFFFu, p, off);
        if ((t & 31) == 0) red[t >> 5] = p;
    }
    __syncthreads();
    if (t == 0) out[g] = red[0] + red[1] + bl3[0];
}

// ---------------- launch (single stream) ----------------
// issue order: count(0), scanlb(1), fillgemm(2), agg1(3) <- ncu capture, agg2(4), mlp(5)
extern "C" void kernel_launch(void* const* d_in, const int* in_sizes, int n_in,
                              void* d_out, int out_size) {
    const float* x   = (const float*)d_in[0];
    const int*   ei  = (const int*)d_in[1];
    const int*   bat = (const int*)d_in[2];
    const float* W1  = (const float*)d_in[3];
    const float* b1  = (const float*)d_in[4];
    const float* W2  = (const float*)d_in[5];
    const float* b2  = (const float*)d_in[6];
    const float* Wl1 = (const float*)d_in[7];
    const float* bl1 = (const float*)d_in[8];
    const float* Wl2 = (const float*)d_in[9];
    const float* bl2 = (const float*)d_in[10];
    const float* Wl3 = (const float*)d_in[11];
    const float* bl3 = (const float*)d_in[12];
    float* out = (float*)d_out;

    int Nn = in_sizes[0] / 128;
    int E  = in_sizes[1] / 2;
    const int* src = ei;
    const int* dst = ei + E;
    int NB = (Nn + 1023) / 1024;

    static void* cntPtr = nullptr;
    if (cntPtr == nullptr) cudaGetSymbolAddress(&cntPtr, g_cnt);

    cudaMemsetAsync(cntPtr, 0, NNODES * sizeof(int), 0);
    {
        int nThreads = (E >> 2) + (E & 3);
        k_count<<<(nThreads + 255) / 256, 256>>>(dst, E);
    }
    k_scanlb<<<NB, 256>>>(Nn);
    k_fillgemm<<<(Nn + 7) / 8, 256>>>(src, dst, x, W1, E, Nn);
    k_agg1<<<(Nn + 7) / 8, 256>>>(b1, W2, Nn);
    k_agg2<<<(Nn + 7) / 8, 256>>>(b2, bat, Nn);
    k_mlp<<<NGRAPH, 128>>>(Wl1, bl1, Wl2, bl2, Wl3, bl3, out);
}

// round 14
// speedup vs baseline: 1.0592x; 1.0592x over previous
#include <cuda_runtime.h>
#include <cuda_fp16.h>
#include <cstdint>

#define NNODES 100000
#define EMAX   1600000
#define NGRAPH 64

// ---------------- device scratch ----------------
__device__ int    g_cnt[NNODES];
__device__ int    g_rowstart[NNODES];
__device__ int    g_cursor[NNODES];
__device__ unsigned long long g_state[128];   // decoupled-lookback state
__device__ int    g_csrsrc[EMAX];
__device__ float  g_dis[NNODES];
__device__ __half g_hs1h[NNODES * 32];    // fp16: dis * (x @ W1)       (row = 64B)
__device__ __half g_hl[NNODES * 32];      // fp16: dis * lrelu(layer1)  (row = 64B)
__device__ int    g_pool[NGRAPH * 64];

#define FLAG_A (1ull << 62)
#define FLAG_P (2ull << 62)

// ---------------- helpers ----------------
__device__ __forceinline__ int fenc(float v) {
    int i = __float_as_int(v);
    return i >= 0 ? i : (i ^ 0x7FFFFFFF);
}
__device__ __forceinline__ float fdec(int i) {
    return __int_as_float(i >= 0 ? i : (i ^ 0x7FFFFFFF));
}
__device__ __forceinline__ float lrelu(float v) { return v > 0.0f ? v : 0.1f * v; }

#define ENC_NEG_INF ((int)0x807FFFFF)
#define FNEG_INF    __int_as_float(0xFF800000)

// ---------------- kernels ----------------

// histogram of dst (int4-vectorized); block 0 also zeroes scan state + inits pool
__global__ void k_count(const int* __restrict__ dst, int E) {
    if (blockIdx.x == 0) {
        if (threadIdx.x < 128) g_state[threadIdx.x] = 0ull;
        for (int i = threadIdx.x; i < NGRAPH * 64; i += 256) g_pool[i] = ENC_NEG_INF;
    }
    int t = blockIdx.x * blockDim.x + threadIdx.x;
    int e4 = E >> 2;
    if (t < e4) {
        int4 d = reinterpret_cast<const int4*>(dst)[t];
        atomicAdd(&g_cnt[d.x], 1);
        atomicAdd(&g_cnt[d.y], 1);
        atomicAdd(&g_cnt[d.z], 1);
        atomicAdd(&g_cnt[d.w], 1);
    } else {
        int e = e4 * 4 + (t - e4);
        if (e < E) atomicAdd(&g_cnt[dst[e]], 1);
    }
}

// single-pass decoupled-lookback exclusive scan of g_cnt -> g_rowstart/g_cursor; also g_dis
__global__ void k_scanlb(int Nn) {
    __shared__ int sT[256];
    __shared__ int sPrefix;
    int t = threadIdx.x;
    int b = blockIdx.x;
    int base = b * 1024 + t * 4;
    int v0 = (base + 0 < Nn) ? g_cnt[base + 0] : 0;
    int v1 = (base + 1 < Nn) ? g_cnt[base + 1] : 0;
    int v2 = (base + 2 < Nn) ? g_cnt[base + 2] : 0;
    int v3 = (base + 3 < Nn) ? g_cnt[base + 3] : 0;
    if (base + 0 < Nn) g_dis[base + 0] = rsqrtf((float)v0 + 1.0f);
    if (base + 1 < Nn) g_dis[base + 1] = rsqrtf((float)v1 + 1.0f);
    if (base + 2 < Nn) g_dis[base + 2] = rsqrtf((float)v2 + 1.0f);
    if (base + 3 < Nn) g_dis[base + 3] = rsqrtf((float)v3 + 1.0f);
    int tot = v0 + v1 + v2 + v3;
    sT[t] = tot;
    __syncthreads();
    for (int off = 1; off < 256; off <<= 1) {
        int x = 0;
        if (t >= off) x = sT[t - off];
        __syncthreads();
        if (t >= off) sT[t] += x;
        __syncthreads();
    }
    int myExc = sT[t] - tot;
    int blockTotal = sT[255];

    if (t == 0) {
        if (b == 0) {
            atomicExch(&g_state[0], FLAG_P | (unsigned int)blockTotal);
            sPrefix = 0;
        } else {
            atomicExch(&g_state[b], FLAG_A | (unsigned int)blockTotal);
            int run = 0;
            int idx = b - 1;
            while (true) {
                unsigned long long s = atomicAdd(&g_state[idx], 0ull);
                unsigned long long fl = s >> 62;
                if (fl == 2ull) { run += (int)(s & 0xFFFFFFFFull); break; }
                if (fl == 1ull) { run += (int)(s & 0xFFFFFFFFull); idx--; }
            }
            atomicExch(&g_state[b], FLAG_P | (unsigned int)(run + blockTotal));
            sPrefix = run;
        }
    }
    __syncthreads();

    int rs = sPrefix + myExc;
    if (base + 0 < Nn) { g_rowstart[base + 0] = rs; g_cursor[base + 0] = rs; } rs += v0;
    if (base + 1 < Nn) { g_rowstart[base + 1] = rs; g_cursor[base + 1] = rs; } rs += v1;
    if (base + 2 < Nn) { g_rowstart[base + 2] = rs; g_cursor[base + 2] = rs; } rs += v2;
    if (base + 3 < Nn) { g_rowstart[base + 3] = rs; g_cursor[base + 3] = rs; }
}

// fused: CSR fill (scatter) + gemm1 (hs1 = fp16(dis * x@W1))
__global__ void k_fillgemm(const int* __restrict__ src, const int* __restrict__ dst,
                           const float* __restrict__ x, const float* __restrict__ W1,
                           int E, int Nn) {
    __shared__ float sW[128 * 32];
    for (int i = threadIdx.x; i < 128 * 32; i += blockDim.x) sW[i] = W1[i];
    __syncthreads();

    int gtid = blockIdx.x * blockDim.x + threadIdx.x;
    int nthr = gridDim.x * blockDim.x;

    int e4 = E >> 2;
    for (int t = gtid; t < e4; t += nthr) {
        int4 d = reinterpret_cast<const int4*>(dst)[t];
        int4 sc = reinterpret_cast<const int4*>(src)[t];
        g_csrsrc[atomicAdd(&g_cursor[d.x], 1)] = sc.x;
        g_csrsrc[atomicAdd(&g_cursor[d.y], 1)] = sc.y;
        g_csrsrc[atomicAdd(&g_cursor[d.z], 1)] = sc.z;
        g_csrsrc[atomicAdd(&g_cursor[d.w], 1)] = sc.w;
    }
    for (int e = e4 * 4 + gtid; e < E; e += nthr)
        g_csrsrc[atomicAdd(&g_cursor[dst[e]], 1)] = src[e];

    int gw = gtid >> 5;
    int nw = nthr >> 5;
    int lane = threadIdx.x & 31;
    for (int node = gw; node < Nn; node += nw) {
        const float* xr = x + (size_t)node * 128;
        float acc = 0.0f;
#pragma unroll
        for (int kt = 0; kt < 4; kt++) {
            float xk = xr[kt * 32 + lane];
#pragma unroll
            for (int kk = 0; kk < 32; kk++) {
                float xv = __shfl_sync(0xFFFFFFFFu, xk, kk);
                acc = fmaf(xv, sW[(kt * 32 + kk) * 32 + lane], acc);
            }
        }
        g_hs1h[(size_t)node * 32 + lane] = __float2half_rn(g_dis[node] * acc);
    }
}

// layer-1 aggregation + lrelu; stores hl = fp16(dis * lrelu)   (NO GEMM2 here)
__global__ void k_agg1(const float* __restrict__ b1, int Nn) {
    int warp = (blockIdx.x * blockDim.x + threadIdx.x) >> 5;
    int lane = threadIdx.x & 31;
    if (warp >= Nn) return;

    int rs = g_rowstart[warp];
    int cnt = g_cnt[warp];
    float a0 = 0.f, a1 = 0.f, a2 = 0.f, a3 = 0.f;
    for (int base = 0; base < cnt; base += 32) {
        int rem = cnt - base;
        int m = rem < 32 ? rem : 32;
        int sidx = 0;
        if (lane < m) sidx = g_csrsrc[rs + base + lane];
        int k = 0;
        for (; k + 4 <= m; k += 4) {
            int s0 = __shfl_sync(0xFFFFFFFFu, sidx, k);
            int s1 = __shfl_sync(0xFFFFFFFFu, sidx, k + 1);
            int s2 = __shfl_sync(0xFFFFFFFFu, sidx, k + 2);
            int s3 = __shfl_sync(0xFFFFFFFFu, sidx, k + 3);
            a0 += __half2float(__ldg(&g_hs1h[(size_t)s0 * 32 + lane]));
            a1 += __half2float(__ldg(&g_hs1h[(size_t)s1 * 32 + lane]));
            a2 += __half2float(__ldg(&g_hs1h[(size_t)s2 * 32 + lane]));
            a3 += __half2float(__ldg(&g_hs1h[(size_t)s3 * 32 + lane]));
        }
        for (; k < m; k++) {
            int s = __shfl_sync(0xFFFFFFFFu, sidx, k);
            a0 += __half2float(__ldg(&g_hs1h[(size_t)s * 32 + lane]));
        }
    }
    float d = g_dis[warp];
    float acc = (a0 + a1) + (a2 + a3);
    float self = __half2float(g_hs1h[(size_t)warp * 32 + lane]);
    float v = lrelu(d * (acc + self) + b1[lane]);
    g_hl[(size_t)warp * 32 + lane] = __float2half_rn(d * v);
}

// layer-2: gather hl (32 feats), t = sum + self, then ONE GEMM2 per node,
// out2 = dis*(t@W2)+b2, fused global max pool (batch sorted)
__global__ void k_agg2(const float* __restrict__ b2, const float* __restrict__ W2,
                       const int* __restrict__ batch, int Nn) {
    __shared__ float sW[32 * 64];
    __shared__ float2 sv[8][32];
    __shared__ int sb[8];
    for (int i = threadIdx.x; i < 32 * 64; i += blockDim.x) sW[i] = W2[i];
    __syncthreads();

    int wid = threadIdx.x >> 5;
    int lane = threadIdx.x & 31;
    int node = blockIdx.x * 8 + wid;
    bool valid = node < Nn;

    if (lane == 0) sb[wid] = valid ? batch[node] : -1;

    if (valid) {
        int rs = g_rowstart[node];
        int cnt = g_cnt[node];
        float a0 = 0.f, a1 = 0.f, a2 = 0.f, a3 = 0.f;
        for (int base = 0; base < cnt; base += 32) {
            int rem = cnt - base;
            int m = rem < 32 ? rem : 32;
            int sidx = 0;
            if (lane < m) sidx = g_csrsrc[rs + base + lane];
            int k = 0;
            for (; k + 4 <= m; k += 4) {
                int s0 = __shfl_sync(0xFFFFFFFFu, sidx, k);
                int s1 = __shfl_sync(0xFFFFFFFFu, sidx, k + 1);
                int s2 = __shfl_sync(0xFFFFFFFFu, sidx, k + 2);
                int s3 = __shfl_sync(0xFFFFFFFFu, sidx, k + 3);
                a0 += __half2float(__ldg(&g_hl[(size_t)s0 * 32 + lane]));
                a1 += __half2float(__ldg(&g_hl[(size_t)s1 * 32 + lane]));
                a2 += __half2float(__ldg(&g_hl[(size_t)s2 * 32 + lane]));
                a3 += __half2float(__ldg(&g_hl[(size_t)s3 * 32 + lane]));
            }
            for (; k < m; k++) {
                int s = __shfl_sync(0xFFFFFFFFu, sidx, k);
                a0 += __half2float(__ldg(&g_hl[(size_t)s * 32 + lane]));
            }
        }
        float selfv = __half2float(g_hl[(size_t)node * 32 + lane]);
        float t = (a0 + a1) + (a2 + a3) + selfv;   // self-loop contributes weight 1 on hl

        // GEMM2 once per node: lane produces output feats (2*lane, 2*lane+1)
        const float2* sWp = reinterpret_cast<const float2*>(sW);
        float o0 = 0.f, o1 = 0.f;
#pragma unroll
        for (int kk = 0; kk < 32; kk++) {
            float xv = __shfl_sync(0xFFFFFFFFu, t, kk);
            float2 w = sWp[kk * 32 + lane];
            o0 = fmaf(xv, w.x, o0);
            o1 = fmaf(xv, w.y, o1);
        }
        float d = g_dis[node];
        float2 bb = reinterpret_cast<const float2*>(b2)[lane];
        float2 o;
        o.x = d * o0 + bb.x;
        o.y = d * o1 + bb.y;
        sv[wid][lane] = o;
    }
    __syncthreads();

    if (threadIdx.x < 64) {
        int f = threadIdx.x;
        int half_ = f >> 1;
        int comp = f & 1;
        int curg = -1;
        float mx = FNEG_INF;
        for (int w = 0; w < 8; w++) {
            int bg = sb[w];
            if (bg < 0) continue;
            float2 p = sv[w][half_];
            float val = comp ? p.y : p.x;
            if (bg != curg) {
                if (curg >= 0) atomicMax(&g_pool[curg * 64 + f], fenc(mx));
                curg = bg;
                mx = FNEG_INF;
            }
            mx = fmaxf(mx, val);
        }
        if (curg >= 0) atomicMax(&g_pool[curg * 64 + f], fenc(mx));
    }
}

// MLP head, one block per graph: 64 -> 128 -> 64 -> 1
__global__ void k_mlp(const float* __restrict__ Wl1, const float* __restrict__ bl1,
                      const float* __restrict__ Wl2, const float* __restrict__ bl2,
                      const float* __restrict__ Wl3, const float* __restrict__ bl3,
                      float* __restrict__ out) {
    __shared__ float sg[64];
    __shared__ float st1[128];
    __shared__ float st2[64];
    int g = blockIdx.x;
    int t = threadIdx.x;

    if (t < 64) sg[t] = fdec(g_pool[g * 64 + t]);
    __syncthreads();
    {
        float s = bl1[t];
#pragma unroll 8
        for (int k = 0; k < 64; k++) s = fmaf(sg[k], Wl1[k * 128 + t], s);
        st1[t] = lrelu(s);
    }
    __syncthreads();
    if (t < 64) {
        float s = bl2[t];
#pragma unroll 8
        for (int k = 0; k < 128; k++) s = fmaf(st1[k], Wl2[k * 64 + t], s);
        st2[t] = lrelu(s);
    }
    __syncthreads();
    __shared__ float red[2];
    if (t < 64) {
        float p = st2[t] * Wl3[t];
#pragma unroll
        for (int off = 16; off > 0; off >>= 1)
            p += __shfl_down_sync(0xFFFFFFFFu, p, off);
        if ((t & 31) == 0) red[t >> 5] = p;
    }
    __syncthreads();
    if (t == 0) out[g] = red[0] + red[1] + bl3[0];
}

// ---------------- launch (single stream) ----------------
// issue order: count(0), scanlb(1), fillgemm(2), agg1(3) <- ncu capture, agg2(4), mlp(5)
extern "C" void kernel_launch(void* const* d_in, const int* in_sizes, int n_in,
                              void* d_out, int out_size) {
    const float* x   = (const float*)d_in[0];
    const int*   ei  = (const int*)d_in[1];
    const int*   bat = (const int*)d_in[2];
    const float* W1  = (const float*)d_in[3];
    const float* b1  = (const float*)d_in[4];
    const float* W2  = (const float*)d_in[5];
    const float* b2  = (const float*)d_in[6];
    const float* Wl1 = (const float*)d_in[7];
    const float* bl1 = (const float*)d_in[8];
    const float* Wl2 = (const float*)d_in[9];
    const float* bl2 = (const float*)d_in[10];
    const float* Wl3 = (const float*)d_in[11];
    const float* bl3 = (const float*)d_in[12];
    float* out = (float*)d_out;

    int Nn = in_sizes[0] / 128;
    int E  = in_sizes[1] / 2;
    const int* src = ei;
    const int* dst = ei + E;
    int NB = (Nn + 1023) / 1024;

    static void* cntPtr = nullptr;
    if (cntPtr == nullptr) cudaGetSymbolAddress(&cntPtr, g_cnt);

    cudaMemsetAsync(cntPtr, 0, NNODES * sizeof(int), 0);
    {
        int nThreads = (E >> 2) + (E & 3);
        k_count<<<(nThreads + 255) / 256, 256>>>(dst, E);
    }
    k_scanlb<<<NB, 256>>>(Nn);
    k_fillgemm<<<(Nn + 7) / 8, 256>>>(src, dst, x, W1, E, Nn);
    k_agg1<<<(Nn + 7) / 8, 256>>>(b1, Nn);
    k_agg2<<<(Nn + 7) / 8, 256>>>(b2, W2, bat, Nn);
    k_mlp<<<NGRAPH, 128>>>(Wl1, bl1, Wl2, bl2, Wl3, bl3, out);
}